// round 4
// baseline (speedup 1.0000x reference)
#include <cuda_runtime.h>
#include <cstdint>
#include <math.h>

#define N_NODES 50000
#define N_EDGES 600000
#define DIM     128
#define DIM4    32
#define NLAYER  5
#define BN_EPS  1e-5f

// ---------------- device scratch ----------------
__device__ float g_h  [N_NODES * DIM];
__device__ float g_agg[N_NODES * DIM];
__device__ float g_mid[N_NODES * 2 * DIM];
__device__ int   g_counts[N_NODES];
__device__ int   g_row[N_NODES + 1];
__device__ int   g_cursor[N_NODES];
__device__ int   g_bsums[64];
__device__ int   g_csr_src[N_EDGES];
__device__ int   g_csr_ea [N_EDGES];
__device__ float g_stats[2 * DIM];
// precomputed weight planes (bf16 pairs packed in u32): 5*128*256/2 = 81920 each
__device__ uint32_t g_w1h[81920], g_w1l[81920], g_w2h[81920], g_w2l[81920];

// ---------------- helpers ----------------
__device__ __forceinline__ uint32_t smem_u32(const void* p) {
    uint32_t a;
    asm("{ .reg .u64 t; cvta.to.shared.u64 t, %1; cvt.u32.u64 %0, t; }"
        : "=r"(a) : "l"(p));
    return a;
}
__device__ __forceinline__ uint32_t pack_hi(float a, float b) {
    return __byte_perm(__float_as_uint(a), __float_as_uint(b), 0x7632);
}
__device__ __forceinline__ uint32_t pack_lo(float a, float b) {
    float ra = a - __uint_as_float(__float_as_uint(a) & 0xFFFF0000u);
    float rb = b - __uint_as_float(__float_as_uint(b) & 0xFFFF0000u);
    uint32_t r;
    asm("cvt.rn.bf16x2.f32 %0, %1, %2;" : "=r"(r) : "f"(rb), "f"(ra));
    return r;
}
__device__ __forceinline__ void ldsm4(uint32_t* r, uint32_t addr) {
    asm volatile("ldmatrix.sync.aligned.m8n8.x4.shared.b16 {%0,%1,%2,%3}, [%4];"
        : "=r"(r[0]), "=r"(r[1]), "=r"(r[2]), "=r"(r[3]) : "r"(addr));
}
__device__ __forceinline__ void ldsm2t(uint32_t* r, uint32_t addr) {
    asm volatile("ldmatrix.sync.aligned.m8n8.x2.trans.shared.b16 {%0,%1}, [%2];"
        : "=r"(r[0]), "=r"(r[1]) : "r"(addr));
}
__device__ __forceinline__ void mma_bf16(float* c, const uint32_t* a, const uint32_t* b) {
    asm volatile("mma.sync.aligned.m16n8k16.row.col.f32.bf16.bf16.f32 "
        "{%0,%1,%2,%3}, {%4,%5,%6,%7}, {%8,%9}, {%0,%1,%2,%3};"
        : "+f"(c[0]), "+f"(c[1]), "+f"(c[2]), "+f"(c[3])
        : "r"(a[0]), "r"(a[1]), "r"(a[2]), "r"(a[3]), "r"(b[0]), "r"(b[1]));
}

// ---------------- setup kernels ----------------
__global__ void k_init_h(const int* __restrict__ x,
                         const float* __restrict__ ae,
                         const float* __restrict__ ce,
                         const float* __restrict__ he) {
    int i = blockIdx.x * blockDim.x + threadIdx.x;
    if (i >= N_NODES * DIM4) return;
    int r = i >> 5, q = i & 31;
    int a = x[r * 3 + 0];
    int c = x[r * 3 + 1];
    int h = x[r * 3 + 2];
    float4 v  = ((const float4*)ae)[a * DIM4 + q];
    float4 v2 = ((const float4*)ce)[c * DIM4 + q];
    float4 v3 = ((const float4*)he)[h * DIM4 + q];
    v.x += v2.x + v3.x; v.y += v2.y + v3.y;
    v.z += v2.z + v3.z; v.w += v2.w + v3.w;
    ((float4*)g_h)[i] = v;
}

// weight precompute: t in [0, 81920): pair of floats from W1 and W2
__global__ void k_wconv(const float* __restrict__ W1, const float* __restrict__ W2) {
    int t = blockIdx.x * blockDim.x + threadIdx.x;
    if (t >= 81920) return;
    float2 a = ((const float2*)W1)[t];
    float2 b = ((const float2*)W2)[t];
    g_w1h[t] = pack_hi(a.x, a.y);
    g_w1l[t] = pack_lo(a.x, a.y);
    g_w2h[t] = pack_hi(b.x, b.y);
    g_w2l[t] = pack_lo(b.x, b.y);
}

__global__ void k_zero_counts() {
    int i = blockIdx.x * blockDim.x + threadIdx.x;
    if (i < N_NODES) g_counts[i] = 0;
}
__global__ void k_hist(const int* __restrict__ ei) {
    int e = blockIdx.x * blockDim.x + threadIdx.x;
    if (e >= N_EDGES) return;
    atomicAdd(&g_counts[ei[N_EDGES + e]], 1);
}
__global__ void k_scan1() {
    __shared__ int sm[1024];
    int t = threadIdx.x;
    int gid = blockIdx.x * 1024 + t;
    int v = (gid < N_NODES) ? g_counts[gid] : 0;
    sm[t] = v;
    __syncthreads();
    for (int off = 1; off < 1024; off <<= 1) {
        int add = (t >= off) ? sm[t - off] : 0;
        __syncthreads();
        sm[t] += add;
        __syncthreads();
    }
    if (gid < N_NODES) g_row[gid] = sm[t] - v;
    if (t == 1023) g_bsums[blockIdx.x] = sm[1023];
}
__global__ void k_scan2(int nb) {
    __shared__ int sm[64];
    int t = threadIdx.x;
    int v = (t < nb) ? g_bsums[t] : 0;
    sm[t] = v;
    __syncthreads();
    for (int off = 1; off < 64; off <<= 1) {
        int add = (t >= off) ? sm[t - off] : 0;
        __syncthreads();
        sm[t] += add;
        __syncthreads();
    }
    if (t < nb) g_bsums[t] = sm[t] - v;
}
__global__ void k_scan3() {
    int gid = blockIdx.x * blockDim.x + threadIdx.x;
    if (gid < N_NODES) {
        int r = g_row[gid] + g_bsums[gid >> 10];
        g_row[gid] = r;
        g_cursor[gid] = r;
    }
    if (gid == 0) g_row[N_NODES] = N_EDGES;
}
__global__ void k_scatter(const int* __restrict__ ei, const int* __restrict__ ea) {
    int e = blockIdx.x * blockDim.x + threadIdx.x;
    if (e >= N_EDGES) return;
    int d = ei[N_EDGES + e];
    int p = atomicAdd(&g_cursor[d], 1);
    g_csr_src[p] = ei[e];
    g_csr_ea[p]  = ea[2 * e] + (ea[2 * e + 1] << 3);
}

__global__ void __launch_bounds__(256) k_agg(const float* __restrict__ e1l,
                                             const float* __restrict__ e2l) {
    __shared__ float4 se[10 * DIM4];
    int tid = threadIdx.x;
    for (int i = tid; i < 10 * DIM4; i += 256) {
        const float* src = (i < 6 * DIM4) ? (e1l + i * 4) : (e2l + (i - 6 * DIM4) * 4);
        se[i] = *(const float4*)src;
    }
    __syncthreads();
    int warp = tid >> 5, lane = tid & 31;
    int v = blockIdx.x * 8 + warp;
    if (v >= N_NODES) return;
    int s0 = g_row[v], s1 = g_row[v + 1];
    float4 acc = make_float4(0.f, 0.f, 0.f, 0.f);
    int e = s0;
    for (; e + 1 < s1; e += 2) {
        int sA  = g_csr_src[e],  sB  = g_csr_src[e + 1];
        int atA = g_csr_ea[e],   atB = g_csr_ea[e + 1];
        float4 hA = ((const float4*)g_h)[sA * DIM4 + lane];
        float4 hB = ((const float4*)g_h)[sB * DIM4 + lane];
        float4 t1A = se[(atA & 7) * DIM4 + lane];
        float4 t2A = se[6 * DIM4 + (atA >> 3) * DIM4 + lane];
        float4 t1B = se[(atB & 7) * DIM4 + lane];
        float4 t2B = se[6 * DIM4 + (atB >> 3) * DIM4 + lane];
        acc.x += (hA.x + t1A.x + t2A.x) + (hB.x + t1B.x + t2B.x);
        acc.y += (hA.y + t1A.y + t2A.y) + (hB.y + t1B.y + t2B.y);
        acc.z += (hA.z + t1A.z + t2A.z) + (hB.z + t1B.z + t2B.z);
        acc.w += (hA.w + t1A.w + t2A.w) + (hB.w + t1B.w + t2B.w);
    }
    if (e < s1) {
        int s  = g_csr_src[e];
        int at = g_csr_ea[e];
        float4 hv = ((const float4*)g_h)[s * DIM4 + lane];
        float4 t1 = se[(at & 7) * DIM4 + lane];
        float4 t2 = se[6 * DIM4 + (at >> 3) * DIM4 + lane];
        acc.x += hv.x + t1.x + t2.x;
        acc.y += hv.y + t1.y + t2.y;
        acc.z += hv.z + t1.z + t2.z;
        acc.w += hv.w + t1.w + t2.w;
    }
    ((float4*)g_agg)[v * DIM4 + lane] = acc;
}

// ---------------- GEMM1: mid = relu(agg @ W1 + b1); out 128 x 256 per CTA ----------------
#define LDTA 136
#define APLANE (128 * LDTA * 2)      // 34816
#define LDTB1 264
#define B1PLANE (128 * LDTB1 * 2)    // 67584
#define SMEM1 (2 * APLANE + 2 * B1PLANE)   // 204800

__global__ void __launch_bounds__(512, 1) k_hmma1(
    int M, const float* __restrict__ A,
    const uint32_t* __restrict__ wh, const uint32_t* __restrict__ wl,
    const float* __restrict__ bias, float* __restrict__ C) {
    extern __shared__ char smem[];
    const uint32_t sb = smem_u32(smem);
    const uint32_t AH = sb, AL = sb + APLANE;
    const uint32_t BH = sb + 2 * APLANE, BL = BH + B1PLANE;
    char* pAH = smem;
    char* pAL = smem + APLANE;
    char* pBH = smem + 2 * APLANE;
    char* pBL = smem + 2 * APLANE + B1PLANE;

    const int tid = threadIdx.x, wid = tid >> 5, lane = tid & 31;
    const int wm = wid >> 3;           // 0..1 (64 rows)
    const int wn = wid & 7;            // 0..7 (32 cols)
    const int rowBase = blockIdx.x << 7;

    // ---- fill A: 128 x 128 fp32 -> hi/lo ----
#pragma unroll
    for (int it = 0; it < 8; it++) {
        int g = tid + it * 512;               // 0..4095
        int r = g >> 5, c4 = (g & 31) << 2;
        float4 v = make_float4(0.f, 0.f, 0.f, 0.f);
        if (rowBase + r < M)
            v = *(const float4*)(A + (size_t)(rowBase + r) * 128 + c4);
        uint2 hi, lo;
        hi.x = pack_hi(v.x, v.y); hi.y = pack_hi(v.z, v.w);
        lo.x = pack_lo(v.x, v.y); lo.y = pack_lo(v.z, v.w);
        int off = (r * LDTA + c4) * 2;
        *(uint2*)(pAH + off) = hi;
        *(uint2*)(pAL + off) = lo;
    }
    // ---- fill B: straight bf16 copy, 128 k-rows x 256 n-cols ----
#pragma unroll
    for (int it = 0; it < 8; it++) {
        int g = tid + it * 512;               // 0..4095 (16B groups)
        int k = g >> 5, n8 = (g & 31) << 3;
        int src = k * 128 + ((g & 31) << 2);  // u32 index
        int off = (k * LDTB1 + n8) * 2;
        *(uint4*)(pBH + off) = *(const uint4*)(wh + src);
        *(uint4*)(pBL + off) = *(const uint4*)(wl + src);
    }
    __syncthreads();

    float acc[4][4][4];
#pragma unroll
    for (int i = 0; i < 4; i++)
#pragma unroll
        for (int j = 0; j < 4; j++)
#pragma unroll
            for (int k = 0; k < 4; k++) acc[i][j][k] = 0.f;

    const int arow = wm * 64 + (lane & 15);
    const int acolSel = (lane >> 4) << 3;
    const int brow = lane & 15;
#pragma unroll
    for (int kk = 0; kk < 8; kk++) {
        uint32_t ah[4][4], al[4][4], bh[4][2], bl[4][2];
        int acol = kk * 16 + acolSel;
#pragma unroll
        for (int mi = 0; mi < 4; mi++) {
            uint32_t ao = (uint32_t)(((arow + mi * 16) * LDTA + acol) * 2);
            ldsm4(ah[mi], AH + ao);
            ldsm4(al[mi], AL + ao);
        }
#pragma unroll
        for (int ni = 0; ni < 4; ni++) {
            uint32_t bo = (uint32_t)(((kk * 16 + brow) * LDTB1 + wn * 32 + ni * 8) * 2);
            ldsm2t(bh[ni], BH + bo);
            ldsm2t(bl[ni], BL + bo);
        }
#pragma unroll
        for (int mi = 0; mi < 4; mi++)
#pragma unroll
            for (int ni = 0; ni < 4; ni++) {
                mma_bf16(acc[mi][ni], ah[mi], bh[ni]);
                mma_bf16(acc[mi][ni], ah[mi], bl[ni]);
                mma_bf16(acc[mi][ni], al[mi], bh[ni]);
            }
    }

    const int rBase = rowBase + wm * 64 + (lane >> 2);
    const int cBase = wn * 32 + (lane & 3) * 2;
#pragma unroll
    for (int mi = 0; mi < 4; mi++)
#pragma unroll
        for (int h = 0; h < 2; h++) {
            int row = rBase + mi * 16 + h * 8;
            if (row < M) {
#pragma unroll
                for (int ni = 0; ni < 4; ni++) {
                    int col = cBase + ni * 8;
                    float2 o;
                    o.x = fmaxf(acc[mi][ni][2 * h + 0] + bias[col], 0.f);
                    o.y = fmaxf(acc[mi][ni][2 * h + 1] + bias[col + 1], 0.f);
                    *(float2*)(C + (size_t)row * 256 + col) = o;
                }
            }
        }
}

// ---------------- GEMM2: h2 = mid @ W2 + b2; out 128 x 128, K=256 ----------------
#define B2PLANE (256 * LDTA * 2)     // 69632
#define SMEM2 (2 * APLANE + 2 * B2PLANE)   // 208896

__global__ void __launch_bounds__(512, 1) k_hmma2(
    int M, const float* __restrict__ A,
    const uint32_t* __restrict__ wh, const uint32_t* __restrict__ wl,
    const float* __restrict__ bias, float* __restrict__ C) {
    extern __shared__ char smem[];
    const uint32_t sb = smem_u32(smem);
    const uint32_t AH = sb, AL = sb + APLANE;
    const uint32_t BH = sb + 2 * APLANE, BL = BH + B2PLANE;
    char* pAH = smem;
    char* pAL = smem + APLANE;
    char* pBH = smem + 2 * APLANE;
    char* pBL = smem + 2 * APLANE + B2PLANE;

    const int tid = threadIdx.x, wid = tid >> 5, lane = tid & 31;
    const int wm = wid >> 3;           // 0..1 (64 rows)
    const int wn = wid & 7;            // 0..7 (16 cols)
    const int rowBase = blockIdx.x << 7;

    // ---- fill B once: 256 k-rows x 128 n-cols bf16 copy ----
#pragma unroll
    for (int it = 0; it < 8; it++) {
        int g = tid + it * 512;               // 0..4095
        int k = g >> 4, n8 = (g & 15) << 3;
        int src = k * 64 + ((g & 15) << 2);
        int off = (k * LDTA + n8) * 2;
        *(uint4*)(pBH + off) = *(const uint4*)(wh + src);
        *(uint4*)(pBL + off) = *(const uint4*)(wl + src);
    }

    float acc[4][2][4];
#pragma unroll
    for (int i = 0; i < 4; i++)
#pragma unroll
        for (int j = 0; j < 2; j++)
#pragma unroll
            for (int k = 0; k < 4; k++) acc[i][j][k] = 0.f;

    const int arow = wm * 64 + (lane & 15);
    const int acolSel = (lane >> 4) << 3;
    const int brow = lane & 15;

    for (int ch = 0; ch < 2; ch++) {
        if (ch) __syncthreads();
        // ---- fill A chunk: 128 rows x 128 k (fp32 -> hi/lo) ----
#pragma unroll
        for (int it = 0; it < 8; it++) {
            int g = tid + it * 512;
            int r = g >> 5, c4 = (g & 31) << 2;
            float4 v = make_float4(0.f, 0.f, 0.f, 0.f);
            if (rowBase + r < M)
                v = *(const float4*)(A + (size_t)(rowBase + r) * 256 + ch * 128 + c4);
            uint2 hi, lo;
            hi.x = pack_hi(v.x, v.y); hi.y = pack_hi(v.z, v.w);
            lo.x = pack_lo(v.x, v.y); lo.y = pack_lo(v.z, v.w);
            int off = (r * LDTA + c4) * 2;
            *(uint2*)(pAH + off) = hi;
            *(uint2*)(pAL + off) = lo;
        }
        __syncthreads();

#pragma unroll
        for (int kk = 0; kk < 8; kk++) {
            uint32_t ah[4][4], al[4][4], bh[2][2], bl[2][2];
            int acol = kk * 16 + acolSel;
#pragma unroll
            for (int mi = 0; mi < 4; mi++) {
                uint32_t ao = (uint32_t)(((arow + mi * 16) * LDTA + acol) * 2);
                ldsm4(ah[mi], AH + ao);
                ldsm4(al[mi], AL + ao);
            }
#pragma unroll
            for (int ni = 0; ni < 2; ni++) {
                uint32_t bo = (uint32_t)(((ch * 128 + kk * 16 + brow) * LDTA
                                          + wn * 16 + ni * 8) * 2);
                ldsm2t(bh[ni], BH + bo);
                ldsm2t(bl[ni], BL + bo);
            }
#pragma unroll
            for (int mi = 0; mi < 4; mi++)
#pragma unroll
                for (int ni = 0; ni < 2; ni++) {
                    mma_bf16(acc[mi][ni], ah[mi], bh[ni]);
                    mma_bf16(acc[mi][ni], ah[mi], bl[ni]);
                    mma_bf16(acc[mi][ni], al[mi], bh[ni]);
                }
        }
    }

    const int rBase = rowBase + wm * 64 + (lane >> 2);
    const int cBase = wn * 16 + (lane & 3) * 2;
#pragma unroll
    for (int mi = 0; mi < 4; mi++)
#pragma unroll
        for (int h = 0; h < 2; h++) {
            int row = rBase + mi * 16 + h * 8;
            if (row < M) {
#pragma unroll
                for (int ni = 0; ni < 2; ni++) {
                    int col = cBase + ni * 8;
                    float2 o;
                    o.x = acc[mi][ni][2 * h + 0] + bias[col];
                    o.y = acc[mi][ni][2 * h + 1] + bias[col + 1];
                    *(float2*)(C + (size_t)row * 128 + col) = o;
                }
            }
        }
}

// ---------------- BN ----------------
__global__ void k_zero_stats() {
    int i = threadIdx.x;
    if (i < 2 * DIM) g_stats[i] = 0.f;
}
__global__ void k_stats(const float* __restrict__ h2) {
    int c = threadIdx.x;
    float s = 0.f, ss = 0.f;
    for (int r = blockIdx.x; r < N_NODES; r += gridDim.x) {
        float v = h2[(size_t)r * DIM + c];
        s += v;
        ss += v * v;
    }
    atomicAdd(&g_stats[c], s);
    atomicAdd(&g_stats[DIM + c], ss);
}
__global__ void k_bn(const float* __restrict__ h2,
                     const float* __restrict__ gamma,
                     const float* __restrict__ beta,
                     float* __restrict__ out, int relu) {
    __shared__ float sc[DIM], sh[DIM];
    int tid = threadIdx.x;
    if (tid < DIM) {
        float mu  = g_stats[tid] * (1.0f / N_NODES);
        float var = g_stats[DIM + tid] * (1.0f / N_NODES) - mu * mu;
        float s = gamma[tid] * rsqrtf(var + BN_EPS);
        sc[tid] = s;
        sh[tid] = beta[tid] - mu * s;
    }
    __syncthreads();
    int i = blockIdx.x * blockDim.x + tid;
    if (i >= N_NODES * DIM4) return;
    int c = (i & 31) * 4;
    float4 v = ((const float4*)h2)[i];
    v.x = v.x * sc[c + 0] + sh[c + 0];
    v.y = v.y * sc[c + 1] + sh[c + 1];
    v.z = v.z * sc[c + 2] + sh[c + 2];
    v.w = v.w * sc[c + 3] + sh[c + 3];
    if (relu) {
        v.x = fmaxf(v.x, 0.f); v.y = fmaxf(v.y, 0.f);
        v.z = fmaxf(v.z, 0.f); v.w = fmaxf(v.w, 0.f);
    }
    ((float4*)out)[i] = v;
}

// ---------------- launch ----------------
extern "C" void kernel_launch(void* const* d_in, const int* in_sizes, int n_in,
                              void* d_out, int out_size) {
    const int*   x     = (const int*)d_in[0];
    const int*   ei    = (const int*)d_in[1];
    const int*   ea    = (const int*)d_in[2];
    const float* atom  = (const float*)d_in[3];
    const float* chir  = (const float*)d_in[4];
    const float* hyb   = (const float*)d_in[5];
    const float* e1    = (const float*)d_in[6];
    const float* e2    = (const float*)d_in[7];
    const float* W1    = (const float*)d_in[8];
    const float* b1    = (const float*)d_in[9];
    const float* W2    = (const float*)d_in[10];
    const float* b2    = (const float*)d_in[11];
    const float* gamma = (const float*)d_in[12];
    const float* beta  = (const float*)d_in[13];
    float* out = (float*)d_out;

    float *pAgg, *pMid, *pH;
    uint32_t *pW1h, *pW1l, *pW2h, *pW2l;
    cudaGetSymbolAddress((void**)&pAgg, g_agg);
    cudaGetSymbolAddress((void**)&pMid, g_mid);
    cudaGetSymbolAddress((void**)&pH,   g_h);
    cudaGetSymbolAddress((void**)&pW1h, g_w1h);
    cudaGetSymbolAddress((void**)&pW1l, g_w1l);
    cudaGetSymbolAddress((void**)&pW2h, g_w2h);
    cudaGetSymbolAddress((void**)&pW2l, g_w2l);

    cudaFuncSetAttribute(k_hmma1, cudaFuncAttributeMaxDynamicSharedMemorySize, SMEM1);
    cudaFuncSetAttribute(k_hmma2, cudaFuncAttributeMaxDynamicSharedMemorySize, SMEM2);

    const int TPB = 256;
    int nbE = (N_EDGES + TPB - 1) / TPB;
    int nbN = (N_NODES + TPB - 1) / TPB;
    int nbF4 = (N_NODES * DIM4) / TPB;

    k_init_h<<<nbF4, TPB>>>(x, atom, chir, hyb);
    k_wconv<<<320, 256>>>(W1, W2);
    k_zero_counts<<<nbN, TPB>>>();
    k_hist<<<nbE, TPB>>>(ei);
    int scanBlocks = (N_NODES + 1023) / 1024;
    k_scan1<<<scanBlocks, 1024>>>();
    k_scan2<<<1, 64>>>(scanBlocks);
    k_scan3<<<nbN, TPB>>>();
    k_scatter<<<nbE, TPB>>>(ei, ea);

    int gemmRows = (N_NODES + 127) / 128;   // 391
    for (int l = 0; l < NLAYER; l++) {
        k_agg<<<(N_NODES + 7) / 8, 256>>>(e1 + (size_t)l * 6 * DIM,
                                          e2 + (size_t)l * 4 * DIM);
        k_hmma1<<<gemmRows, 512, SMEM1>>>(N_NODES, pAgg,
                                          pW1h + l * 16384, pW1l + l * 16384,
                                          b1 + (size_t)l * 2 * DIM, pMid);
        k_hmma2<<<gemmRows, 512, SMEM2>>>(N_NODES, pMid,
                                          pW2h + l * 16384, pW2l + l * 16384,
                                          b2 + (size_t)l * DIM, pAgg);
        k_zero_stats<<<1, 256>>>();
        k_stats<<<512, 128>>>(pAgg);
        int last = (l == NLAYER - 1);
        k_bn<<<nbF4, TPB>>>(pAgg, gamma + (size_t)l * DIM, beta + (size_t)l * DIM,
                            last ? out : pH, last ? 0 : 1);
    }
}